// round 13
// baseline (speedup 1.0000x reference)
#include <cuda_runtime.h>
#include <cstdint>
#include <stdint.h>

#define B_SZ   256
#define T_SZ   2048
#define N_SZ   128
#define NPAIRS (B_SZ * T_SZ)   // 524288

#define WROW   132
#define WROW4  33
#define BSROW  129

// Scratch (device globals — no allocation allowed)
__device__ __align__(16) float  g_h[NPAIRS * 2];  // hidden, [t][b] float2 layout
__device__ __align__(16) float2 g_c[NPAIRS];      // input proj, [t][b] float2
__device__ __align__(16) float  g_q0[N_SZ];       // Q[:,0]
__device__ __align__(16) float  g_q1[N_SZ];       // Q[:,1]

__device__ __forceinline__ float fast_rcp(float x) {
    float r;
    asm("rcp.approx.f32 %0, %1;" : "=f"(r) : "f"(x));
    return r;
}

// ---------------------------------------------------------------------------
// Kernel 0: input projection  c[t][b] = 0.1 * wIn @ u[b,t,:]
// ---------------------------------------------------------------------------
__global__ void __launch_bounds__(256) proj_kernel(const float* __restrict__ u,
                                                   const float* __restrict__ wIn) {
    const float I00 = 0.1f * __ldg(wIn + 0), I01 = 0.1f * __ldg(wIn + 1),
                I02 = 0.1f * __ldg(wIn + 2);
    const float I10 = 0.1f * __ldg(wIn + 3), I11 = 0.1f * __ldg(wIn + 4),
                I12 = 0.1f * __ldg(wIn + 5);

    int p4 = (int)blockIdx.x * 256 + (int)threadIdx.x;   // 0..131071
    int b  = p4 >> 9;
    int t0 = (p4 & 511) << 2;

    const float4* up = (const float4*)(u + (size_t)b * (T_SZ * 3) + (size_t)t0 * 3);
    float4 v0 = __ldg(up + 0);
    float4 v1 = __ldg(up + 1);
    float4 v2 = __ldg(up + 2);

    float2* outp = g_c + (size_t)t0 * B_SZ + b;
    outp[0]         = make_float2(fmaf(I00, v0.x, fmaf(I01, v0.y, I02 * v0.z)),
                                  fmaf(I10, v0.x, fmaf(I11, v0.y, I12 * v0.z)));
    outp[B_SZ]      = make_float2(fmaf(I00, v0.w, fmaf(I01, v1.x, I02 * v1.y)),
                                  fmaf(I10, v0.w, fmaf(I11, v1.x, I12 * v1.y)));
    outp[2 * B_SZ]  = make_float2(fmaf(I00, v1.z, fmaf(I01, v1.w, I02 * v2.x)),
                                  fmaf(I10, v1.z, fmaf(I11, v1.w, I12 * v2.x)));
    outp[3 * B_SZ]  = make_float2(fmaf(I00, v2.y, fmaf(I01, v2.z, I02 * v2.w)),
                                  fmaf(I10, v2.y, fmaf(I11, v2.z, I12 * v2.w)));
}

// ---------------------------------------------------------------------------
// Kernel 1: Cayley solve (ONE block, 256 threads) — panel-4 blocked GE,
// warp-0 panel factorization, two block barriers per panel.
// ---------------------------------------------------------------------------
__global__ void __launch_bounds__(256) solve_kernel(
        const float* __restrict__ matB) {
    extern __shared__ float smem[];
    const int tid  = threadIdx.x;
    const int lane = tid & 31;
    const int wid  = tid >> 5;

    float*  Wf     = smem;                           // [128][132]
    float4* W4     = (float4*)smem;                  // stride 33
    float*  Bs     = smem + N_SZ * WROW;             // [128][129]
    float*  prowf  = Bs + N_SZ * BSROW;              // [4][132]
    float4* prow4  = (float4*)prowf;                 // [4][33]
    float*  rinv_s = prowf + 4 * WROW;               // [4]
    __shared__ float z0s[N_SZ], z1s[N_SZ];
    const int i = tid;                               // row (threads 0..127)

    // ---- stage matB (coalesced float4) ----
    for (int idx = tid; idx < N_SZ * 32; idx += 256) {
        int r = idx >> 5, c4 = idx & 31;
        float4 v = ((const float4*)matB)[r * 32 + c4];
        float* dst = Bs + r * BSROW + c4 * 4;
        dst[0] = v.x; dst[1] = v.y; dst[2] = v.z; dst[3] = v.w;
    }
    __syncthreads();

    // ---- build augmented [I+A | e0 e1] ----
    if (i < N_SZ) {
        float* wr = Wf + i * WROW;
        #pragma unroll 4
        for (int j = 0; j < N_SZ; j++) {
            float a = Bs[i * BSROW + j] - Bs[j * BSROW + i];
            wr[j] = (i == j ? 1.0f : 0.0f) + a;
        }
        wr[128] = (i == 0) ? 1.0f : 0.0f;
        wr[129] = (i == 1) ? 1.0f : 0.0f;
        wr[130] = 0.0f; wr[131] = 0.0f;
    }
    __syncthreads();

    // ---- 32 panels, 2 barriers each ----
    for (int p = 0; p < 32; p++) {
        // panel factorization: warp 0 only
        if (wid == 0) {
            const unsigned FULL = 0xffffffffu;
            float4 pr[4];
            float4 pr32[4];
            float  rv[4];
            #pragma unroll
            for (int m = 0; m < 4; m++) {
                const int k = 4 * p + m;
                float4 v   = W4[k * WROW4 + lane];
                float4 v32 = make_float4(0.f, 0.f, 0.f, 0.f);
                if (lane == 0) v32 = W4[k * WROW4 + 32];
                #pragma unroll
                for (int j = 0; j < 3; j++) {
                    if (j < m) {
                        float elem = (j == 0) ? v.x : ((j == 1) ? v.y : v.z);
                        float fj = __shfl_sync(FULL, elem * rv[j], p);
                        v.x = fmaf(-fj, pr[j].x, v.x);
                        v.y = fmaf(-fj, pr[j].y, v.y);
                        v.z = fmaf(-fj, pr[j].z, v.z);
                        v.w = fmaf(-fj, pr[j].w, v.w);
                        if (lane == 0) {
                            v32.x = fmaf(-fj, pr32[j].x, v32.x);
                            v32.y = fmaf(-fj, pr32[j].y, v32.y);
                            v32.z = fmaf(-fj, pr32[j].z, v32.z);
                            v32.w = fmaf(-fj, pr32[j].w, v32.w);
                        }
                    }
                }
                float dg = (m == 0) ? v.x : ((m == 1) ? v.y : ((m == 2) ? v.z : v.w));
                float rm = __shfl_sync(FULL, fast_rcp(dg), p);
                rv[m] = rm;
                pr[m] = v;
                prow4[m * WROW4 + lane] = v;
                if (lane == 0) {
                    pr32[m] = v32;
                    prow4[m * WROW4 + 32] = v32;
                    rinv_s[m] = rm;
                }
            }
        }
        __syncthreads();   // bar 1: prow + rinv published

        // factors in registers + rank-4 update (rows below panel)
        if (i < N_SZ && i > 4 * p + 3) {
            float4 cp  = W4[i * WROW4 + p];
            float4 pp0 = prow4[0 * WROW4 + p];
            float4 pp1 = prow4[1 * WROW4 + p];
            float4 pp2 = prow4[2 * WROW4 + p];
            float r0 = rinv_s[0], r1 = rinv_s[1], r2 = rinv_s[2], r3 = rinv_s[3];

            float f0 = cp.x * r0;
            cp.y = fmaf(-f0, pp0.y, cp.y);
            float f1 = cp.y * r1;
            cp.z = fmaf(-f1, pp1.z, fmaf(-f0, pp0.z, cp.z));
            float f2 = cp.z * r2;
            cp.w = fmaf(-f2, pp2.w, fmaf(-f1, pp1.w, fmaf(-f0, pp0.w, cp.w)));
            float f3 = cp.w * r3;

            const float4* q0r = prow4 + 0 * WROW4;
            const float4* q1r = prow4 + 1 * WROW4;
            const float4* q2r = prow4 + 2 * WROW4;
            const float4* q3r = prow4 + 3 * WROW4;
            float4* wr = W4 + i * WROW4;
            #pragma unroll 4
            for (int g = p + 1; g < WROW4; g++) {
                float4 a  = wr[g];
                float4 q0 = q0r[g], q1 = q1r[g], q2 = q2r[g], q3 = q3r[g];
                a.x = fmaf(-f0, q0.x, fmaf(-f1, q1.x, fmaf(-f2, q2.x, fmaf(-f3, q3.x, a.x))));
                a.y = fmaf(-f0, q0.y, fmaf(-f1, q1.y, fmaf(-f2, q2.y, fmaf(-f3, q3.y, a.y))));
                a.z = fmaf(-f0, q0.z, fmaf(-f1, q1.z, fmaf(-f2, q2.z, fmaf(-f3, q3.z, a.z))));
                a.w = fmaf(-f0, q0.w, fmaf(-f1, q1.w, fmaf(-f2, q2.w, fmaf(-f3, q3.w, a.w))));
                wr[g] = a;
            }
        }
        // copyback of finalized pivot rows by the idle upper half
        if (tid >= 128) {
            for (int idx = tid - 128; idx < 4 * WROW4; idx += 128)
                W4[(4 * p + idx / WROW4) * WROW4 + (idx % WROW4)] = prow4[idx];
        }
        __syncthreads();   // bar 2: panel complete
    }

    // ---- back substitution (2 RHS) ----
    for (int k = N_SZ - 1; k >= 0; k--) {
        if (i < N_SZ) {
            float rinv = fast_rcp(Wf[k * WROW + k]);
            float zk0 = Wf[k * WROW + 128] * rinv;
            float zk1 = Wf[k * WROW + 129] * rinv;
            if (i < k) {
                float a = Wf[i * WROW + k];
                Wf[i * WROW + 128] = fmaf(-a, zk0, Wf[i * WROW + 128]);
                Wf[i * WROW + 129] = fmaf(-a, zk1, Wf[i * WROW + 129]);
            } else if (i == k) {
                z0s[k] = zk0;
                z1s[k] = zk1;
            }
        }
        __syncthreads();
    }

    // ---- q_r = (I - A) z_r ----
    if (i < N_SZ) {
        float q0 = z0s[i], q1 = z1s[i];
        #pragma unroll 4
        for (int k = 0; k < N_SZ; k++) {
            float a = Bs[i * BSROW + k] - Bs[k * BSROW + i];
            q0 = fmaf(-a, z0s[k], q0);
            q1 = fmaf(-a, z1s[k], q1);
        }
        g_q0[i] = q0;
        g_q1[i] = q1;
    }
}

// ---------------------------------------------------------------------------
// Kernel 2: leaky RNN — 8 blocks x 32 threads (1 warp), one sequence each,
// 4-buffer rotation reading g_c (coalesced, L2-resident). R11-proven.
// ---------------------------------------------------------------------------
__global__ void __launch_bounds__(32) rnn_kernel(const float* __restrict__ wRec) {
    const int lane = threadIdx.x;
    const int seq  = (int)blockIdx.x * 32 + lane;

    const float W00 = 0.1f * wRec[0], W01 = 0.1f * wRec[1];
    const float W10 = 0.1f * wRec[2], W11 = 0.1f * wRec[3];

    const float2* gc = g_c;
    float2* hp = (float2*)g_h;
    float y0 = 0.0f, y1 = 0.0f;

    #define RNN_STEP2(CC, TT)                                               \
        {                                                                   \
            float a0 = fmaf(0.9f, y0, CC.x);                                \
            float a1 = fmaf(0.9f, y1, CC.y);                                \
            float r0 = fmaxf(y0, 0.0f);                                     \
            float r1 = fmaxf(y1, 0.0f);                                     \
            float t0 = fmaf(W00, r0, a0);                                   \
            float t1 = fmaf(W10, r0, a1);                                   \
            y0 = fmaf(W01, r1, t0);                                         \
            y1 = fmaf(W11, r1, t1);                                         \
            hp[(TT) * B_SZ + seq] = make_float2(y0, y1);                    \
        }

    #define LOADG(P, G)                                                     \
        {                                                                   \
            const float2* cp_ = gc + (size_t)(G) * 8 * B_SZ + seq;          \
            P##0 = __ldg(cp_ + 0 * B_SZ); P##1 = __ldg(cp_ + 1 * B_SZ);     \
            P##2 = __ldg(cp_ + 2 * B_SZ); P##3 = __ldg(cp_ + 3 * B_SZ);     \
            P##4 = __ldg(cp_ + 4 * B_SZ); P##5 = __ldg(cp_ + 5 * B_SZ);     \
            P##6 = __ldg(cp_ + 6 * B_SZ); P##7 = __ldg(cp_ + 7 * B_SZ);     \
        }

    #define RNN_G8(P, TB)                                                   \
        {                                                                   \
            RNN_STEP2(P##0, (TB) + 0); RNN_STEP2(P##1, (TB) + 1);           \
            RNN_STEP2(P##2, (TB) + 2); RNN_STEP2(P##3, (TB) + 3);           \
            RNN_STEP2(P##4, (TB) + 4); RNN_STEP2(P##5, (TB) + 5);           \
            RNN_STEP2(P##6, (TB) + 6); RNN_STEP2(P##7, (TB) + 7);           \
        }

    float2 A0, A1, A2, A3, A4, A5, A6, A7;
    float2 B0, B1, B2, B3, B4, B5, B6, B7;
    float2 C0, C1, C2, C3, C4, C5, C6, C7;
    float2 D0, D1, D2, D3, D4, D5, D6, D7;

    LOADG(A, 0);
    LOADG(B, 1);
    LOADG(C, 2);

    #pragma unroll 1
    for (int g = 0; g < 252; g += 4) {
        LOADG(D, g + 3);
        RNN_G8(A, (g + 0) * 8);
        LOADG(A, g + 4);
        RNN_G8(B, (g + 1) * 8);
        LOADG(B, g + 5);
        RNN_G8(C, (g + 2) * 8);
        LOADG(C, g + 6);
        RNN_G8(D, (g + 3) * 8);
    }
    LOADG(D, 255);
    RNN_G8(A, 252 * 8);
    RNN_G8(B, 253 * 8);
    RNN_G8(C, 254 * 8);
    RNN_G8(D, 255 * 8);

    #undef RNN_G8
    #undef LOADG
    #undef RNN_STEP2
}

// ---------------------------------------------------------------------------
// Kernel 3: expand  out[b,t,:] = h0 * q0[:] + h1 * q1[:]
// ---------------------------------------------------------------------------
__global__ void __launch_bounds__(256, 8) expand_kernel(float* __restrict__ out) {
    const int lane = threadIdx.x & 31;
    const int wid  = ((int)blockIdx.x * (int)blockDim.x + (int)threadIdx.x) >> 5;
    const int nw   = ((int)gridDim.x * (int)blockDim.x) >> 5;

    const float4 q0 = ((const float4*)g_q0)[lane];
    const float4 q1 = ((const float4*)g_q1)[lane];
    const float2* hp = (const float2*)g_h;
    float4* o = (float4*)out;

    const int ntask = NPAIRS / 4;
    for (int task = wid; task < ntask; task += nw) {
        int q = task << 2;          // q = b*2048 + t
        int b = q >> 11;
        int t = q & (T_SZ - 1);

        float2 h0 = hp[(t + 0) * B_SZ + b];
        float2 h1 = hp[(t + 1) * B_SZ + b];
        float2 h2 = hp[(t + 2) * B_SZ + b];
        float2 h3 = hp[(t + 3) * B_SZ + b];

        size_t base = (size_t)q * 32 + lane;
        float4 v;
        v.x = fmaf(h0.x, q0.x, h0.y * q1.x);
        v.y = fmaf(h0.x, q0.y, h0.y * q1.y);
        v.z = fmaf(h0.x, q0.z, h0.y * q1.z);
        v.w = fmaf(h0.x, q0.w, h0.y * q1.w);
        __stcs(&o[base], v);
        v.x = fmaf(h1.x, q0.x, h1.y * q1.x);
        v.y = fmaf(h1.x, q0.y, h1.y * q1.y);
        v.z = fmaf(h1.x, q0.z, h1.y * q1.z);
        v.w = fmaf(h1.x, q0.w, h1.y * q1.w);
        __stcs(&o[base + 32], v);
        v.x = fmaf(h2.x, q0.x, h2.y * q1.x);
        v.y = fmaf(h2.x, q0.y, h2.y * q1.y);
        v.z = fmaf(h2.x, q0.z, h2.y * q1.z);
        v.w = fmaf(h2.x, q0.w, h2.y * q1.w);
        __stcs(&o[base + 64], v);
        v.x = fmaf(h3.x, q0.x, h3.y * q1.x);
        v.y = fmaf(h3.x, q0.y, h3.y * q1.y);
        v.z = fmaf(h3.x, q0.z, h3.y * q1.z);
        v.w = fmaf(h3.x, q0.w, h3.y * q1.w);
        __stcs(&o[base + 96], v);
    }
}

// ---------------------------------------------------------------------------
extern "C" void kernel_launch(void* const* d_in, const int* in_sizes, int n_in,
                              void* d_out, int out_size) {
    // u = 1572864, matB = 16384, wIn = 6, wRec = 4
    const float *u = nullptr, *matB = nullptr, *wIn = nullptr, *wRec = nullptr;
    for (int i = 0; i < n_in; i++) {
        switch (in_sizes[i]) {
            case 1572864: u    = (const float*)d_in[i]; break;
            case 16384:   matB = (const float*)d_in[i]; break;
            case 6:       wIn  = (const float*)d_in[i]; break;
            case 4:       wRec = (const float*)d_in[i]; break;
        }
    }

    const int smem = (N_SZ * WROW + N_SZ * BSROW + 4 * WROW + 4)
                     * (int)sizeof(float);   // ~135.8 KB
    cudaFuncSetAttribute(solve_kernel,
                         cudaFuncAttributeMaxDynamicSharedMemorySize, smem);

    // 0) input projection: u -> g_c
    proj_kernel<<<512, 256>>>(u, wIn);

    // 1) Cayley solve (ncu -s 5 -c 1 lands here on iteration 2)
    solve_kernel<<<1, 256, smem>>>(matB);

    // 2) leaky RNN: 8 blocks x 1 warp, 32 sequences each
    rnn_kernel<<<8, 32>>>(wRec);

    // 3) expand: write-bandwidth bound
    expand_kernel<<<1184, 256>>>((float*)d_out);
}

// round 14
// speedup vs baseline: 1.6404x; 1.6404x over previous
#include <cuda_runtime.h>
#include <cstdint>
#include <stdint.h>

#define B_SZ   256
#define T_SZ   2048
#define N_SZ   128
#define NPAIRS (B_SZ * T_SZ)   // 524288

#define WROW   132
#define WROW4  33
#define BSROW  129

// Scratch (device globals — no allocation allowed)
__device__ __align__(16) float  g_h[NPAIRS * 2];  // hidden, [t][b] float2 layout
__device__ __align__(16) float2 g_c[NPAIRS];      // input proj, [t][b] float2
__device__ __align__(16) float  g_q0[N_SZ];       // Q[:,0]
__device__ __align__(16) float  g_q1[N_SZ];       // Q[:,1]

__device__ __forceinline__ float fast_rcp(float x) {
    float r;
    asm("rcp.approx.f32 %0, %1;" : "=f"(r) : "f"(x));
    return r;
}

// ---------------------------------------------------------------------------
// Kernel 0: input projection  c[t][b] = 0.1 * wIn @ u[b,t,:]
// ---------------------------------------------------------------------------
__global__ void __launch_bounds__(256) proj_kernel(const float* __restrict__ u,
                                                   const float* __restrict__ wIn) {
    const float I00 = 0.1f * __ldg(wIn + 0), I01 = 0.1f * __ldg(wIn + 1),
                I02 = 0.1f * __ldg(wIn + 2);
    const float I10 = 0.1f * __ldg(wIn + 3), I11 = 0.1f * __ldg(wIn + 4),
                I12 = 0.1f * __ldg(wIn + 5);

    int p4 = (int)blockIdx.x * 256 + (int)threadIdx.x;   // 0..131071
    int b  = p4 >> 9;
    int t0 = (p4 & 511) << 2;

    const float4* up = (const float4*)(u + (size_t)b * (T_SZ * 3) + (size_t)t0 * 3);
    float4 v0 = __ldg(up + 0);
    float4 v1 = __ldg(up + 1);
    float4 v2 = __ldg(up + 2);

    float2* outp = g_c + (size_t)t0 * B_SZ + b;
    outp[0]         = make_float2(fmaf(I00, v0.x, fmaf(I01, v0.y, I02 * v0.z)),
                                  fmaf(I10, v0.x, fmaf(I11, v0.y, I12 * v0.z)));
    outp[B_SZ]      = make_float2(fmaf(I00, v0.w, fmaf(I01, v1.x, I02 * v1.y)),
                                  fmaf(I10, v0.w, fmaf(I11, v1.x, I12 * v1.y)));
    outp[2 * B_SZ]  = make_float2(fmaf(I00, v1.z, fmaf(I01, v1.w, I02 * v2.x)),
                                  fmaf(I10, v1.z, fmaf(I11, v1.w, I12 * v2.x)));
    outp[3 * B_SZ]  = make_float2(fmaf(I00, v2.y, fmaf(I01, v2.z, I02 * v2.w)),
                                  fmaf(I10, v2.y, fmaf(I11, v2.z, I12 * v2.w)));
}

// ---------------------------------------------------------------------------
// Phase 1:
//   block 0:     Cayley solve — panel-4 GE, warp-0 factorization, 2-half
//                (256-thread, 8-warp) rank-4 trailing update
//   blocks 1..8: leaky RNN — 1 warp, 32 seqs, 8-buffer deep rotation
// ---------------------------------------------------------------------------
__global__ void __launch_bounds__(256) phase1_kernel(
        const float* __restrict__ matB,
        const float* __restrict__ wRec) {
    extern __shared__ float smem[];
    const int tid  = threadIdx.x;
    const int lane = tid & 31;
    const int wid  = tid >> 5;

    if (blockIdx.x == 0) {
        // ================= Cayley solve =================
        float*  Wf     = smem;                           // [128][132]
        float4* W4     = (float4*)smem;                  // stride 33
        float*  Bs     = smem + N_SZ * WROW;             // [128][129]
        float*  prowf  = Bs + N_SZ * BSROW;              // [4][132]
        float4* prow4  = (float4*)prowf;                 // [4][33]
        float*  rinv_s = prowf + 4 * WROW;               // [4]
        __shared__ float z0s[N_SZ], z1s[N_SZ];
        const int row  = tid & 127;
        const int half = tid >> 7;

        // ---- stage matB (coalesced float4) ----
        for (int idx = tid; idx < N_SZ * 32; idx += 256) {
            int r = idx >> 5, c4 = idx & 31;
            float4 v = ((const float4*)matB)[r * 32 + c4];
            float* dst = Bs + r * BSROW + c4 * 4;
            dst[0] = v.x; dst[1] = v.y; dst[2] = v.z; dst[3] = v.w;
        }
        __syncthreads();

        // ---- build augmented [I+A | e0 e1] ----
        if (half == 0) {
            float* wr = Wf + row * WROW;
            #pragma unroll 4
            for (int j = 0; j < N_SZ; j++) {
                float a = Bs[row * BSROW + j] - Bs[j * BSROW + row];
                wr[j] = (row == j ? 1.0f : 0.0f) + a;
            }
            wr[128] = (row == 0) ? 1.0f : 0.0f;
            wr[129] = (row == 1) ? 1.0f : 0.0f;
            wr[130] = 0.0f; wr[131] = 0.0f;
        }
        __syncthreads();

        // ---- 32 panels, 2 barriers each ----
        for (int p = 0; p < 32; p++) {
            // panel factorization: warp 0 only (proven R12/R13 code)
            if (wid == 0) {
                const unsigned FULL = 0xffffffffu;
                float4 pr[4];
                float4 pr32[4];
                float  rv[4];
                #pragma unroll
                for (int m = 0; m < 4; m++) {
                    const int k = 4 * p + m;
                    float4 v   = W4[k * WROW4 + lane];
                    float4 v32 = make_float4(0.f, 0.f, 0.f, 0.f);
                    if (lane == 0) v32 = W4[k * WROW4 + 32];
                    #pragma unroll
                    for (int j = 0; j < 3; j++) {
                        if (j < m) {
                            float elem = (j == 0) ? v.x : ((j == 1) ? v.y : v.z);
                            float fj = __shfl_sync(FULL, elem * rv[j], p);
                            v.x = fmaf(-fj, pr[j].x, v.x);
                            v.y = fmaf(-fj, pr[j].y, v.y);
                            v.z = fmaf(-fj, pr[j].z, v.z);
                            v.w = fmaf(-fj, pr[j].w, v.w);
                            if (lane == 0) {
                                v32.x = fmaf(-fj, pr32[j].x, v32.x);
                                v32.y = fmaf(-fj, pr32[j].y, v32.y);
                                v32.z = fmaf(-fj, pr32[j].z, v32.z);
                                v32.w = fmaf(-fj, pr32[j].w, v32.w);
                            }
                        }
                    }
                    float dg = (m == 0) ? v.x : ((m == 1) ? v.y : ((m == 2) ? v.z : v.w));
                    float rm = __shfl_sync(FULL, fast_rcp(dg), p);
                    rv[m] = rm;
                    pr[m] = v;
                    prow4[m * WROW4 + lane] = v;
                    if (lane == 0) {
                        pr32[m] = v32;
                        prow4[m * WROW4 + 32] = v32;
                        rinv_s[m] = rm;
                    }
                }
            }
            __syncthreads();   // bar 1: prow + rinv published

            if (row > 4 * p + 3) {
                // factors in registers (computed by BOTH halves, cheap)
                float4 cp  = W4[row * WROW4 + p];
                float4 pp0 = prow4[0 * WROW4 + p];
                float4 pp1 = prow4[1 * WROW4 + p];
                float4 pp2 = prow4[2 * WROW4 + p];
                float r0 = rinv_s[0], r1 = rinv_s[1], r2 = rinv_s[2], r3 = rinv_s[3];

                float f0 = cp.x * r0;
                cp.y = fmaf(-f0, pp0.y, cp.y);
                float f1 = cp.y * r1;
                cp.z = fmaf(-f1, pp1.z, fmaf(-f0, pp0.z, cp.z));
                float f2 = cp.z * r2;
                cp.w = fmaf(-f2, pp2.w, fmaf(-f1, pp1.w, fmaf(-f0, pp0.w, cp.w)));
                float f3 = cp.w * r3;

                // rank-4 update: this half handles groups of its parity
                const float4* q0r = prow4 + 0 * WROW4;
                const float4* q1r = prow4 + 1 * WROW4;
                const float4* q2r = prow4 + 2 * WROW4;
                const float4* q3r = prow4 + 3 * WROW4;
                float4* wr = W4 + row * WROW4;
                #pragma unroll 2
                for (int g = p + 1 + half; g < WROW4; g += 2) {
                    float4 a  = wr[g];
                    float4 q0 = q0r[g], q1 = q1r[g], q2 = q2r[g], q3 = q3r[g];
                    a.x = fmaf(-f0, q0.x, fmaf(-f1, q1.x, fmaf(-f2, q2.x, fmaf(-f3, q3.x, a.x))));
                    a.y = fmaf(-f0, q0.y, fmaf(-f1, q1.y, fmaf(-f2, q2.y, fmaf(-f3, q3.y, a.y))));
                    a.z = fmaf(-f0, q0.z, fmaf(-f1, q1.z, fmaf(-f2, q2.z, fmaf(-f3, q3.z, a.z))));
                    a.w = fmaf(-f0, q0.w, fmaf(-f1, q1.w, fmaf(-f2, q2.w, fmaf(-f3, q3.w, a.w))));
                    wr[g] = a;
                }
            } else {
                // idle rows (<= panel): copy finalized pivot rows back into W
                int cidx   = row * 2 + half;         // 0 .. 8(p+1)-1
                int stride = 8 * (p + 1);
                for (int idx = cidx; idx < 4 * WROW4; idx += stride)
                    W4[(4 * p + idx / WROW4) * WROW4 + (idx % WROW4)] = prow4[idx];
            }
            __syncthreads();   // bar 2: panel complete
        }

        // ---- back substitution (2 RHS) ----
        for (int k = N_SZ - 1; k >= 0; k--) {
            if (half == 0) {
                float rinv = fast_rcp(Wf[k * WROW + k]);
                float zk0 = Wf[k * WROW + 128] * rinv;
                float zk1 = Wf[k * WROW + 129] * rinv;
                if (row < k) {
                    float a = Wf[row * WROW + k];
                    Wf[row * WROW + 128] = fmaf(-a, zk0, Wf[row * WROW + 128]);
                    Wf[row * WROW + 129] = fmaf(-a, zk1, Wf[row * WROW + 129]);
                } else if (row == k) {
                    z0s[k] = zk0;
                    z1s[k] = zk1;
                }
            }
            __syncthreads();
        }

        // ---- q_r = (I - A) z_r ----
        if (half == 0) {
            float q0 = z0s[row], q1 = z1s[row];
            #pragma unroll 4
            for (int k = 0; k < N_SZ; k++) {
                float a = Bs[row * BSROW + k] - Bs[k * BSROW + row];
                q0 = fmaf(-a, z0s[k], q0);
                q1 = fmaf(-a, z1s[k], q1);
            }
            g_q0[row] = q0;
            g_q1[row] = q1;
        }
    } else {
        // ====== Leaky RNN: 1 warp per block, 32 seqs, 8-buffer rotation =====
        if (tid >= 32) return;
        const int seq = ((int)blockIdx.x - 1) * 32 + tid;

        const float W00 = 0.1f * wRec[0], W01 = 0.1f * wRec[1];
        const float W10 = 0.1f * wRec[2], W11 = 0.1f * wRec[3];

        const float2* gc = g_c;
        float2* hp = (float2*)g_h;
        float y0 = 0.0f, y1 = 0.0f;

        #define RNN_STEP2(CC, TT)                                               \
            {                                                                   \
                float a0 = fmaf(0.9f, y0, CC.x);                                \
                float a1 = fmaf(0.9f, y1, CC.y);                                \
                float r0 = fmaxf(y0, 0.0f);                                     \
                float r1 = fmaxf(y1, 0.0f);                                     \
                float t0 = fmaf(W00, r0, a0);                                   \
                float t1 = fmaf(W10, r0, a1);                                   \
                y0 = fmaf(W01, r1, t0);                                         \
                y1 = fmaf(W11, r1, t1);                                         \
                hp[(TT) * B_SZ + seq] = make_float2(y0, y1);                    \
            }

        // clamped group load (groups >= 256 re-load 255; dead data)
        #define LOADG(P, G)                                                     \
            {                                                                   \
                int gg_ = (G) < 255 ? (G) : 255;                                \
                const float2* cp_ = gc + (size_t)gg_ * 8 * B_SZ + seq;          \
                P##0 = __ldg(cp_ + 0 * B_SZ); P##1 = __ldg(cp_ + 1 * B_SZ);     \
                P##2 = __ldg(cp_ + 2 * B_SZ); P##3 = __ldg(cp_ + 3 * B_SZ);     \
                P##4 = __ldg(cp_ + 4 * B_SZ); P##5 = __ldg(cp_ + 5 * B_SZ);     \
                P##6 = __ldg(cp_ + 6 * B_SZ); P##7 = __ldg(cp_ + 7 * B_SZ);     \
            }

        #define RNN_G8(P, TB)                                                   \
            {                                                                   \
                RNN_STEP2(P##0, (TB) + 0); RNN_STEP2(P##1, (TB) + 1);           \
                RNN_STEP2(P##2, (TB) + 2); RNN_STEP2(P##3, (TB) + 3);           \
                RNN_STEP2(P##4, (TB) + 4); RNN_STEP2(P##5, (TB) + 5);           \
                RNN_STEP2(P##6, (TB) + 6); RNN_STEP2(P##7, (TB) + 7);           \
            }

        float2 A0, A1, A2, A3, A4, A5, A6, A7;
        float2 B0, B1, B2, B3, B4, B5, B6, B7;
        float2 C0, C1, C2, C3, C4, C5, C6, C7;
        float2 D0, D1, D2, D3, D4, D5, D6, D7;
        float2 E0, E1, E2, E3, E4, E5, E6, E7;
        float2 F0, F1, F2, F3, F4, F5, F6, F7;
        float2 G0, G1, G2, G3, G4, G5, G6, G7;
        float2 H0, H1, H2, H3, H4, H5, H6, H7;

        LOADG(A, 0); LOADG(B, 1); LOADG(C, 2); LOADG(D, 3);
        LOADG(E, 4); LOADG(F, 5); LOADG(G, 6);

        // 256 groups of 8 steps; 8-buffer rotation, loads ~7 groups ahead
        #pragma unroll 1
        for (int g = 0; g < 256; g += 8) {
            LOADG(H, g + 7);
            RNN_G8(A, (g + 0) * 8);
            LOADG(A, g + 8);
            RNN_G8(B, (g + 1) * 8);
            LOADG(B, g + 9);
            RNN_G8(C, (g + 2) * 8);
            LOADG(C, g + 10);
            RNN_G8(D, (g + 3) * 8);
            LOADG(D, g + 11);
            RNN_G8(E, (g + 4) * 8);
            LOADG(E, g + 12);
            RNN_G8(F, (g + 5) * 8);
            LOADG(F, g + 13);
            RNN_G8(G, (g + 6) * 8);
            LOADG(G, g + 14);
            RNN_G8(H, (g + 7) * 8);
        }

        #undef RNN_G8
        #undef LOADG
        #undef RNN_STEP2
    }
}

// ---------------------------------------------------------------------------
// Phase 2: out[b,t,:] = h0 * q0[:] + h1 * q1[:]
// ---------------------------------------------------------------------------
__global__ void __launch_bounds__(256, 8) expand_kernel(float* __restrict__ out) {
    const int lane = threadIdx.x & 31;
    const int wid  = ((int)blockIdx.x * (int)blockDim.x + (int)threadIdx.x) >> 5;
    const int nw   = ((int)gridDim.x * (int)blockDim.x) >> 5;

    const float4 q0 = ((const float4*)g_q0)[lane];
    const float4 q1 = ((const float4*)g_q1)[lane];
    const float2* hp = (const float2*)g_h;
    float4* o = (float4*)out;

    const int ntask = NPAIRS / 4;
    for (int task = wid; task < ntask; task += nw) {
        int q = task << 2;          // q = b*2048 + t
        int b = q >> 11;
        int t = q & (T_SZ - 1);

        float2 h0 = hp[(t + 0) * B_SZ + b];
        float2 h1 = hp[(t + 1) * B_SZ + b];
        float2 h2 = hp[(t + 2) * B_SZ + b];
        float2 h3 = hp[(t + 3) * B_SZ + b];

        size_t base = (size_t)q * 32 + lane;
        float4 v;
        v.x = fmaf(h0.x, q0.x, h0.y * q1.x);
        v.y = fmaf(h0.x, q0.y, h0.y * q1.y);
        v.z = fmaf(h0.x, q0.z, h0.y * q1.z);
        v.w = fmaf(h0.x, q0.w, h0.y * q1.w);
        __stcs(&o[base], v);
        v.x = fmaf(h1.x, q0.x, h1.y * q1.x);
        v.y = fmaf(h1.x, q0.y, h1.y * q1.y);
        v.z = fmaf(h1.x, q0.z, h1.y * q1.z);
        v.w = fmaf(h1.x, q0.w, h1.y * q1.w);
        __stcs(&o[base + 32], v);
        v.x = fmaf(h2.x, q0.x, h2.y * q1.x);
        v.y = fmaf(h2.x, q0.y, h2.y * q1.y);
        v.z = fmaf(h2.x, q0.z, h2.y * q1.z);
        v.w = fmaf(h2.x, q0.w, h2.y * q1.w);
        __stcs(&o[base + 64], v);
        v.x = fmaf(h3.x, q0.x, h3.y * q1.x);
        v.y = fmaf(h3.x, q0.y, h3.y * q1.y);
        v.z = fmaf(h3.x, q0.z, h3.y * q1.z);
        v.w = fmaf(h3.x, q0.w, h3.y * q1.w);
        __stcs(&o[base + 96], v);
    }
}

// ---------------------------------------------------------------------------
extern "C" void kernel_launch(void* const* d_in, const int* in_sizes, int n_in,
                              void* d_out, int out_size) {
    // u = 1572864, matB = 16384, wIn = 6, wRec = 4
    const float *u = nullptr, *matB = nullptr, *wIn = nullptr, *wRec = nullptr;
    for (int i = 0; i < n_in; i++) {
        switch (in_sizes[i]) {
            case 1572864: u    = (const float*)d_in[i]; break;
            case 16384:   matB = (const float*)d_in[i]; break;
            case 6:       wIn  = (const float*)d_in[i]; break;
            case 4:       wRec = (const float*)d_in[i]; break;
        }
    }

    const int smem = (N_SZ * WROW + N_SZ * BSROW + 4 * WROW + 4)
                     * (int)sizeof(float);   // ~135.8 KB
    cudaFuncSetAttribute(phase1_kernel,
                         cudaFuncAttributeMaxDynamicSharedMemorySize, smem);

    // 0) input projection: u -> g_c
    proj_kernel<<<512, 256>>>(u, wIn);

    // 1) block 0: solve;  blocks 1..8: RNN (fused, overlapped)
    phase1_kernel<<<9, 256, smem>>>(matB, wRec);

    // 2) expand: write-bandwidth bound
    expand_kernel<<<1184, 256>>>((float*)d_out);
}